// round 16
// baseline (speedup 1.0000x reference)
#include <cuda_runtime.h>
#include <cuda_bf16.h>
#include <mma.h>
#include <math.h>

using namespace nvcuda;

#define NPOS 32768
#define NB 2

// ---------------- scratch (device globals) ----------------
__device__ __align__(16) float g_y2 [NB*64*NPOS];   // proj2+shortcut output
__device__ __align__(16) float g_qkv[NB*192*NPOS];
__device__ __align__(16) float g_x5 [NB*64*NPOS];   // shortcut
__device__ __align__(16) float g_u  [NB*64*NPOS];
__device__ __align__(16) float g_a  [NB*64*NPOS];
__device__ __align__(16) float g_b  [NB*64*NPOS];
__device__ __align__(16) __nv_bfloat16 g_bclh[NB*64*NPOS];  // channels-last bf16 of g_b
__device__ float g_scale[256];                      // RAW sum-of-squares
__device__ float g_attn[NB*4*16*16];                // RAW gram
__device__ __align__(16) float g_qkvT[64*192];
__device__ __align__(16) float g_p1T[64*64];
__device__ __align__(16) float g_c1T[64*64];
__device__ __align__(16) float g_p2T[64*64];
__device__ __align__(16) float g_oT [64*64];
__device__ __align__(16) __nv_bfloat16 g_offWh[27*96*64];   // bf16 [tap][o][c]
__device__ __align__(16) __nv_bfloat16 g_dcnWh[27*64*64];   // bf16 [tap][o][c]
__device__ float g_c1bf[64];

// ---------------- one mega prep kernel (+ zero attn/scale) ----------------
__global__ void k_prep(const float* __restrict__ qkvw, const float* __restrict__ p1w,
                       const float* __restrict__ c1w, const float* __restrict__ p2w,
                       const float* __restrict__ ow,  const float* __restrict__ offw,
                       const float* __restrict__ dcnw, const float* __restrict__ c1b,
                       const float* __restrict__ dcnb) {
    if (blockIdx.x == 0) {
        for (int i = threadIdx.x; i < 2048 + 256; i += 256) {
            if (i < 2048) g_attn[i] = 0.f; else g_scale[i - 2048] = 0.f;
        }
    }
    int i = blockIdx.x * 256 + threadIdx.x;
    if (i < 165888) {                      // offWh [27][96][64]
        int c = i & 63, o = (i >> 6) % 96, k = i / (96 * 64);
        g_offWh[i] = __float2bfloat16((o < 81) ? offw[(o * 64 + c) * 27 + k] : 0.f);
        return;
    }
    int j = i - 165888;
    if (j < 110592) {                      // dcnWh [27][64][64]
        int c = j & 63, o = (j >> 6) & 63, k = j >> 12;
        g_dcnWh[j] = __float2bfloat16(dcnw[(o * 64 + c) * 27 + k]);
        return;
    }
    j -= 110592;
    if (j < 12288) { int c = j / 192, o = j % 192; g_qkvT[j] = qkvw[o * 64 + c]; return; }
    j -= 12288;
    if (j < 4096) { int c = j >> 6, o = j & 63; g_p1T[j] = p1w[o * 64 + c]; return; }
    j -= 4096;
    if (j < 4096) { int c = j >> 6, o = j & 63; g_c1T[j] = c1w[o * 64 + c]; return; }
    j -= 4096;
    if (j < 4096) { int c = j >> 6, o = j & 63; g_p2T[j] = p2w[o * 64 + c]; return; }
    j -= 4096;
    if (j < 4096) { int c = j >> 6, o = j & 63; g_oT[j] = ow[o * 64 + c]; return; }
    j -= 4096;
    if (j < 64) {
        float s = c1b[j];
        for (int c = 0; c < 64; c++) s += c1w[j * 64 + c] * dcnb[c];
        g_c1bf[j] = s;
    }
}

// ---------------- transpose [B,64,N] -> channels-last bf16 [B,N,64] ----------------
__global__ void k_to_cl(const float* __restrict__ in) {
    __shared__ float tile[64][65];
    int b = blockIdx.y; int n0 = blockIdx.x * 64;
    #pragma unroll
    for (int it = 0; it < 16; it++) {
        int idx = it * 256 + threadIdx.x;
        int c = idx >> 6, r = idx & 63;
        tile[r][c] = in[((size_t)b * 64 + c) * NPOS + n0 + r];
    }
    __syncthreads();
    #pragma unroll
    for (int it = 0; it < 8; it++) {                 // bf16x2 writes
        int idx = it * 256 + threadIdx.x;
        int r = idx >> 5, c2 = idx & 31;
        __nv_bfloat162 v = __floats2bfloat162_rn(tile[r][c2 * 2], tile[r][c2 * 2 + 1]);
        *(__nv_bfloat162*)&g_bclh[((size_t)b * NPOS + n0 + r) * 64 + c2 * 2] = v;
    }
}

// ---------------- qkv: 2 halves per position; each thread 96 of 192 outputs ----------------
__global__ void __launch_bounds__(256) k_qkv(const float* __restrict__ x,
                                             float* __restrict__ out) {
    int b = blockIdx.y;
    int p = threadIdx.x & 127, half = threadIdx.x >> 7;
    int n = blockIdx.x * 128 + p;
    const float4* xp = (const float4*)(x + ((size_t)b * NPOS + n) * 64);
    float xv[64];
    #pragma unroll
    for (int q = 0; q < 16; q++) {
        float4 v = xp[q];
        xv[q*4+0] = v.x; xv[q*4+1] = v.y; xv[q*4+2] = v.z; xv[q*4+3] = v.w;
    }
    #pragma unroll 1
    for (int g = 0; g < 6; g++) {
        int oc = half * 6 + g;
        float acc[16];
        #pragma unroll
        for (int j = 0; j < 16; j++) acc[j] = 0.f;
        #pragma unroll
        for (int c = 0; c < 64; c++) {
            float xc = xv[c];
            const float4* w4 = (const float4*)(g_qkvT + c * 192 + oc * 16);
            #pragma unroll
            for (int q = 0; q < 4; q++) {
                float4 w = w4[q];
                acc[q*4+0] += w.x * xc; acc[q*4+1] += w.y * xc;
                acc[q*4+2] += w.z * xc; acc[q*4+3] += w.w * xc;
            }
        }
        #pragma unroll
        for (int j = 0; j < 16; j++)
            out[((size_t)b * 192 + oc * 16 + j) * NPOS + n] = acc[j];
    }
}

// ---------------- gram q.k^T (2x2 register-blocked) + raw sumsq ----------------
__global__ void k_gram() {
    int bh = blockIdx.y; int b = bh >> 2, h = bh & 3;
    int n0 = blockIdx.x * 256;
    __shared__ float qt[16 * 257], kt[16 * 257];
    #pragma unroll
    for (int it = 0; it < 16; it++) {
        qt[it * 257 + threadIdx.x] =
            g_qkv[((size_t)b * 192 + h * 16 + it) * NPOS + n0 + threadIdx.x];
        kt[it * 257 + threadIdx.x] =
            g_qkv[((size_t)b * 192 + 64 + h * 16 + it) * NPOS + n0 + threadIdx.x];
    }
    __syncthreads();
    int t = threadIdx.x;
    {
        int i = t >> 4, j = t & 15;
        float sq = 0.f, sk = 0.f;
        #pragma unroll
        for (int m = 0; m < 16; m++) {
            float a = qt[j * 257 + i * 16 + m]; sq += a * a;
            float bb2 = kt[j * 257 + i * 16 + m]; sk += bb2 * bb2;
        }
        atomicAdd(&g_scale[b * 64 + h * 16 + j], sq);
        atomicAdd(&g_scale[128 + b * 64 + h * 16 + j], sk);
    }
    if (t < 128) {
        int half = t >> 6, tile = t & 63;
        int i0 = (tile >> 3) * 2, j0 = (tile & 7) * 2;
        const float* q0p = qt + i0 * 257 + half * 128;
        const float* q1p = q0p + 257;
        const float* k0p = kt + j0 * 257 + half * 128;
        const float* k1p = k0p + 257;
        float a00 = 0.f, a01 = 0.f, a10 = 0.f, a11 = 0.f;
        #pragma unroll 8
        for (int nn = 0; nn < 128; nn++) {
            float q0 = q0p[nn], q1 = q1p[nn];
            float k0 = k0p[nn], k1 = k1p[nn];
            a00 += q0 * k0; a01 += q0 * k1;
            a10 += q1 * k0; a11 += q1 * k1;
        }
        atomicAdd(&g_attn[(bh * 16 + i0) * 16 + j0], a00);
        atomicAdd(&g_attn[(bh * 16 + i0) * 16 + j0 + 1], a01);
        atomicAdd(&g_attn[(bh * 16 + i0 + 1) * 16 + j0], a10);
        atomicAdd(&g_attn[(bh * 16 + i0 + 1) * 16 + j0 + 1], a11);
    }
}

// ---------------- softmax + attn@v + LN1 + proj1/gelu; 2 halves per position ----------------
__global__ void __launch_bounds__(256) k_xca_ln_p1(const float* __restrict__ temp,
        const float* __restrict__ nw, const float* __restrict__ nb,
        const float* __restrict__ p1b) {
    int b = blockIdx.y;
    __shared__ float asm_s[4 * 256];
    __shared__ float red1[256], red2[256];
    __shared__ float X[128 * 65];                    // normalized x5 tile [p][c]
    if (threadIdx.x < 64) {
        int h = threadIdx.x >> 4, i = threadIdx.x & 15;
        float sq = 1.f / fmaxf(sqrtf(g_scale[b * 64 + h * 16 + i]), 1e-12f);
        float tt = temp[h];
        float v[16], m = -1e30f;
        #pragma unroll
        for (int j = 0; j < 16; j++) {
            float sk = 1.f / fmaxf(sqrtf(g_scale[128 + b * 64 + h * 16 + j]), 1e-12f);
            v[j] = g_attn[(b * 4 + h) * 256 + i * 16 + j] * sq * sk * tt;
            m = fmaxf(m, v[j]);
        }
        float s = 0.f;
        #pragma unroll
        for (int j = 0; j < 16; j++) { v[j] = expf(v[j] - m); s += v[j]; }
        float inv = 1.f / s;
        #pragma unroll
        for (int j = 0; j < 16; j++) asm_s[h * 256 + i * 16 + j] = v[j] * inv;
    }
    __syncthreads();

    int p = threadIdx.x & 127, half = threadIdx.x >> 7;
    int n = blockIdx.x * 128 + p;
    float acc[32];
    #pragma unroll
    for (int c = 0; c < 32; c++) acc[c] = 0.f;
    #pragma unroll
    for (int hh = 0; hh < 2; hh++) {
        int h = half * 2 + hh;
        const float* vb = g_qkv + ((size_t)b * 192 + 128 + h * 16) * NPOS + n;
        const float* ab = asm_s + h * 256;
        #pragma unroll
        for (int j = 0; j < 16; j++) {
            float vv = vb[(size_t)j * NPOS];
            #pragma unroll
            for (int i = 0; i < 16; i++) acc[hh * 16 + i] += ab[i * 16 + j] * vv;
        }
    }
    float s1 = 0.f;
    #pragma unroll
    for (int c = 0; c < 32; c++) s1 += acc[c];
    red1[p * 2 + half] = s1;
    __syncthreads();
    float mean = (red1[p * 2] + red1[p * 2 + 1]) * (1.f / 64.f);
    float s2 = 0.f;
    #pragma unroll
    for (int c = 0; c < 32; c++) { float d = acc[c] - mean; s2 += d * d; }
    red2[p * 2 + half] = s2;
    __syncthreads();
    float rs = rsqrtf((red2[p * 2] + red2[p * 2 + 1]) * (1.f / 64.f) + 1e-5f);
    #pragma unroll
    for (int c = 0; c < 32; c++) {
        int cg = half * 32 + c;
        float v = (acc[c] - mean) * rs * nw[cg] + nb[cg];
        acc[c] = v;
        X[p * 65 + cg] = v;
        g_x5[((size_t)b * 64 + cg) * NPOS + n] = v;
    }
    __syncthreads();
    float a2[32];
    #pragma unroll
    for (int j = 0; j < 32; j++) a2[j] = p1b[half * 32 + j];
    #pragma unroll
    for (int c = 0; c < 64; c++) {
        float xc = X[p * 65 + c];
        const float4* w4 = (const float4*)(g_p1T + c * 64 + half * 32);
        #pragma unroll
        for (int q = 0; q < 8; q++) {
            float4 w = w4[q];
            a2[q*4+0] += w.x * xc; a2[q*4+1] += w.y * xc;
            a2[q*4+2] += w.z * xc; a2[q*4+3] += w.w * xc;
        }
    }
    #pragma unroll
    for (int j = 0; j < 32; j++) {
        float v = a2[j];
        v = 0.5f * v * (1.f + erff(v * 0.70710678118654752f));
        g_u[((size_t)b * 64 + half * 32 + j) * NPOS + n] = v;
    }
}

// ---------------- dw5: k=5, dil=1, pad=2; 8 z-outputs per thread ----------------
__global__ void __launch_bounds__(256) k_dw5(const float* __restrict__ in,
        const float* __restrict__ w, const float* __restrict__ bias,
        float* __restrict__ out) {
    __shared__ float ws[125];
    int bc = blockIdx.y, c = bc & 63;
    for (int i = threadIdx.x; i < 125; i += 256) ws[i] = w[c * 125 + i];
    __syncthreads();
    int task = blockIdx.x * 256 + threadIdx.x;
    int g = task >> 10, yx = task & 1023;
    int y = yx >> 5, x = yx & 31;
    int z0 = g * 8;
    const float* inp = in + (size_t)bc * NPOS;
    float bv = bias[c];
    float acc[8];
    #pragma unroll
    for (int j = 0; j < 8; j++) acc[j] = bv;
    #pragma unroll 1
    for (int ky = 0; ky < 5; ky++) {
        int yy = y + ky - 2; if ((unsigned)yy >= 32u) continue;
        #pragma unroll 1
        for (int kx = 0; kx < 5; kx++) {
            int xx = x + kx - 2; if ((unsigned)xx >= 32u) continue;
            const float* col = inp + yy * 32 + xx;
            float vals[12];
            #pragma unroll
            for (int t = 0; t < 12; t++) {
                int zz = z0 + t - 2;
                vals[t] = ((unsigned)zz < 32u) ? col[zz * 1024] : 0.f;
            }
            float wc[5];
            #pragma unroll
            for (int kz = 0; kz < 5; kz++) wc[kz] = ws[(kz * 5 + ky) * 5 + kx];
            #pragma unroll
            for (int j = 0; j < 8; j++)
                #pragma unroll
                for (int kz = 0; kz < 5; kz++)
                    acc[j] += wc[kz] * vals[j + kz];
        }
    }
    #pragma unroll
    for (int j = 0; j < 8; j++)
        out[(size_t)bc * NPOS + (z0 + j) * 1024 + y * 32 + x] = acc[j];
}

// ---------------- dw7: k=7, dil=3, pad=9; mod-3 z-lattice column per thread ----------------
__global__ void __launch_bounds__(256) k_dw7(const float* __restrict__ in,
        const float* __restrict__ w, const float* __restrict__ bias,
        float* __restrict__ out) {
    __shared__ float ws[343];
    int bc = blockIdx.y, c = bc & 63;
    for (int i = threadIdx.x; i < 343; i += 256) ws[i] = w[c * 343 + i];
    __syncthreads();
    int task = blockIdx.x * 256 + threadIdx.x;
    int r = task >> 10, yx = task & 1023;
    int y = yx >> 5, x = yx & 31;
    int nz = (r == 2) ? 10 : 11;
    const float* inp = in + (size_t)bc * NPOS;
    float bv = bias[c];
    float acc[11];
    #pragma unroll
    for (int j = 0; j < 11; j++) acc[j] = bv;
    #pragma unroll 1
    for (int ky = 0; ky < 7; ky++) {
        int yy = y + ky * 3 - 9; if ((unsigned)yy >= 32u) continue;
        #pragma unroll 1
        for (int kx = 0; kx < 7; kx++) {
            int xx = x + kx * 3 - 9; if ((unsigned)xx >= 32u) continue;
            const float* col = inp + yy * 32 + xx;
            float vals[17];
            #pragma unroll
            for (int t = 0; t < 17; t++) {
                int m = t - 3;
                vals[t] = (m >= 0 && m < nz) ? col[(r + 3 * m) * 1024] : 0.f;
            }
            float wc[7];
            #pragma unroll
            for (int kz = 0; kz < 7; kz++) wc[kz] = ws[(kz * 7 + ky) * 7 + kx];
            #pragma unroll
            for (int j = 0; j < 11; j++)
                #pragma unroll
                for (int kz = 0; kz < 7; kz++)
                    acc[j] += wc[kz] * vals[j + kz];
        }
    }
    #pragma unroll
    for (int j = 0; j < 11; j++)
        if (j < nz) out[(size_t)bc * NPOS + (r + 3 * j) * 1024 + y * 32 + x] = acc[j];
}

// ================= fused offconv + dcn — WARP-AUTONOMOUS (no block barriers) =================
// Each warp owns 16 positions end-to-end: staging strip, offsets, gather, and all
// output channels (phase 1: 96 rows = 6 m-tiles; phase 2: 64 rows = 4 m-tiles).
#define SLDW 72    // bf16 elements per strip row (64 + pad)

__global__ void __launch_bounds__(256) k_offdcn_mma(const float* __restrict__ offb) {
    __shared__ __align__(16) __nv_bfloat16 S[8 * 16 * SLDW];   // per-warp strips (18.4 KB)
    __shared__ __align__(16) __nv_bfloat16 OFS[8 * 96 * 16];   // per-warp offsets (24.6 KB)

    int b = blockIdx.y;
    int n0 = blockIdx.x * 128;
    int t = threadIdx.x, w = t >> 5, lane = t & 31;
    __nv_bfloat16* Sw = S + w * 16 * SLDW;
    __nv_bfloat16* Ow = OFS + w * 96 * 16;
    int nw0 = n0 + w * 16;
    int zB = nw0 >> 10, yW = (nw0 >> 5) & 31, x0 = nw0 & 31;   // warp-uniform z,y; x0 in {0,16}
    int pl = lane >> 3, gg = lane & 7;                          // 4 positions x 8 chunks per pass

    const uint4* in4 = (const uint4*)g_bclh + (size_t)b * NPOS * 8;

    // ---------- phase 1: offsets conv (64 -> 96 rows, 81 real), warp-local ----------
    {
        wmma::fragment<wmma::accumulator,16,16,16,float> acc[6];
        #pragma unroll
        for (int mi = 0; mi < 6; mi++) wmma::fill_fragment(acc[mi], 0.f);

        for (int k = 0; k < 27; k++) {
            int dz = k / 9 - 1, dy = (k / 3) % 3 - 1, dx = k % 3 - 1;
            int zz = zB + dz, yy = yW + dy;
            bool zyok = ((unsigned)zz < 32u) && ((unsigned)yy < 32u);
            int rowbase = zz * 1024 + yy * 32;
            #pragma unroll
            for (int pass = 0; pass < 4; pass++) {
                int pos = pass * 4 + pl;
                int xx = x0 + pos + dx;
                uint4 v = make_uint4(0u, 0u, 0u, 0u);
                if (zyok && (unsigned)xx < 32u)
                    v = in4[(size_t)(rowbase + xx) * 8 + gg];
                *(uint4*)&Sw[pos * SLDW + gg * 8] = v;
            }
            __syncwarp();
            #pragma unroll
            for (int ks = 0; ks < 4; ks++) {
                wmma::fragment<wmma::matrix_b,16,16,16,__nv_bfloat16,wmma::col_major> bf;
                wmma::load_matrix_sync(bf, &Sw[ks * 16], SLDW);
                #pragma unroll
                for (int mi = 0; mi < 6; mi++) {
                    wmma::fragment<wmma::matrix_a,16,16,16,__nv_bfloat16,wmma::row_major> af;
                    wmma::load_matrix_sync(af,
                        g_offWh + ((size_t)k * 96 + mi * 16) * 64 + ks * 16, 64);
                    wmma::mma_sync(acc[mi], af, bf, acc[mi]);
                }
            }
            __syncwarp();
        }
        // stage fragments through Sw (float scratch, 1 KB of 2.3 KB strip) -> Ow bf16
        float* stg = (float*)Sw;
        #pragma unroll
        for (int mi = 0; mi < 6; mi++) {
            wmma::store_matrix_sync(stg, acc[mi], 16, wmma::mem_row_major);
            __syncwarp();
            #pragma unroll
            for (int e = 0; e < 8; e++) {
                int idx = e * 32 + lane;
                int rr = idx >> 4, cc = idx & 15;
                Ow[(mi * 16 + rr) * 16 + cc] = __float2bfloat16(stg[rr * 16 + cc]);
            }
            __syncwarp();
        }
    }

    // ---------- phase 2: deformable conv, warp-local ----------
    {
        wmma::fragment<wmma::accumulator,16,16,16,float> acc[4];
        #pragma unroll
        for (int mi = 0; mi < 4; mi++) wmma::fill_fragment(acc[mi], 0.f);

        for (int k = 0; k < 27; k++) {
            int kz = k / 9 - 1, ky = (k / 3) % 3 - 1, kx = k % 3 - 1;
            float ob0 = offb[k * 3 + 0], ob1 = offb[k * 3 + 1], ob2 = offb[k * 3 + 2];
            #pragma unroll
            for (int pass = 0; pass < 4; pass++) {
                int pos = pass * 4 + pl;
                int x = x0 + pos;
                float pz = (float)(zB + kz) + __bfloat162float(Ow[(k * 3 + 0) * 16 + pos]) + ob0;
                float py = (float)(yW + ky) + __bfloat162float(Ow[(k * 3 + 1) * 16 + pos]) + ob1;
                float px = (float)(x + kx)  + __bfloat162float(Ow[(k * 3 + 2) * 16 + pos]) + ob2;
                float fz = floorf(pz), fy = floorf(py), fx = floorf(px);
                float wz = pz - fz, wy = py - fy, wx = px - fx;
                int iz = (int)fz, iy = (int)fy, ix = (int)fx;
                float2 s0 = make_float2(0.f,0.f), s1 = make_float2(0.f,0.f);
                float2 s2 = make_float2(0.f,0.f), s3 = make_float2(0.f,0.f);
                #pragma unroll
                for (int m = 0; m < 8; m++) {
                    int az = iz + (m >> 2), ay = iy + ((m >> 1) & 1), ax = ix + (m & 1);
                    bool ok = ((unsigned)az < 32u) && ((unsigned)ay < 32u) && ((unsigned)ax < 32u);
                    float cw = ((m >> 2) ? wz : 1.f - wz) * (((m >> 1) & 1) ? wy : 1.f - wy)
                               * ((m & 1) ? wx : 1.f - wx);
                    cw = ok ? cw : 0.f;
                    int ci = (min(max(az,0),31) * 32 + min(max(ay,0),31)) * 32 + min(max(ax,0),31);
                    uint4 v = in4[(size_t)ci * 8 + gg];
                    float2 f0 = __bfloat1622float2(*(__nv_bfloat162*)&v.x);
                    float2 f1 = __bfloat1622float2(*(__nv_bfloat162*)&v.y);
                    float2 f2 = __bfloat1622float2(*(__nv_bfloat162*)&v.z);
                    float2 f3 = __bfloat1622float2(*(__nv_bfloat162*)&v.w);
                    s0.x += cw * f0.x; s0.y += cw * f0.y;
                    s1.x += cw * f1.x; s1.y += cw * f1.y;
                    s2.x += cw * f2.x; s2.y += cw * f2.y;
                    s3.x += cw * f3.x; s3.y += cw * f3.y;
                }
                uint4 ov;
                __nv_bfloat162 o0 = __floats2bfloat162_rn(s0.x, s0.y);
                __nv_bfloat162 o1 = __floats2bfloat162_rn(s1.x, s1.y);
                __nv_bfloat162 o2 = __floats2bfloat162_rn(s2.x, s2.y);
                __nv_bfloat162 o3 = __floats2bfloat162_rn(s3.x, s3.y);
                ov.x = *(unsigned*)&o0; ov.y = *(unsigned*)&o1;
                ov.z = *(unsigned*)&o2; ov.w = *(unsigned*)&o3;
                *(uint4*)&Sw[pos * SLDW + gg * 8] = ov;
            }
            __syncwarp();
            #pragma unroll
            for (int ks = 0; ks < 4; ks++) {
                wmma::fragment<wmma::matrix_b,16,16,16,__nv_bfloat16,wmma::col_major> bf;
                wmma::load_matrix_sync(bf, &Sw[ks * 16], SLDW);
                #pragma unroll
                for (int mi = 0; mi < 4; mi++) {
                    wmma::fragment<wmma::matrix_a,16,16,16,__nv_bfloat16,wmma::row_major> af;
                    wmma::load_matrix_sync(af,
                        g_dcnWh + ((size_t)k * 64 + mi * 16) * 64 + ks * 16, 64);
                    wmma::mma_sync(acc[mi], af, bf, acc[mi]);
                }
            }
            __syncwarp();
        }
        #pragma unroll
        for (int mi = 0; mi < 4; mi++)
            wmma::store_matrix_sync(g_a + ((size_t)b * 64 + mi * 16) * NPOS + nw0,
                                    acc[mi], NPOS, wmma::mem_row_major);
    }
}

// ---------------- fused c1*u + proj2 + shortcut; 2 halves per position ----------------
__global__ void __launch_bounds__(256) k_c1p2(const float* __restrict__ p2b) {
    __shared__ float TV[128 * 65];
    int b = blockIdx.y;
    int p = threadIdx.x & 127, half = threadIdx.x >> 7;
    int n = blockIdx.x * 128 + p;
    const float* ap = g_a + (size_t)b * 64 * NPOS + n;
    float av[64];
    #pragma unroll
    for (int c = 0; c < 64; c++) av[c] = ap[(size_t)c * NPOS];
    float tv[32];
    #pragma unroll
    for (int o = 0; o < 32; o++) tv[o] = g_c1bf[half * 32 + o];
    #pragma unroll
    for (int c = 0; c < 64; c++) {
        float xc = av[c];
        const float4* w4 = (const float4*)(g_c1T + c * 64 + half * 32);
        #pragma unroll
        for (int q = 0; q < 8; q++) {
            float4 w = w4[q];
            tv[q*4+0] += w.x * xc; tv[q*4+1] += w.y * xc;
            tv[q*4+2] += w.z * xc; tv[q*4+3] += w.w * xc;
        }
    }
    const float* up = g_u + (size_t)b * 64 * NPOS + n;
    #pragma unroll
    for (int o = 0; o < 32; o++) {
        tv[o] *= up[(size_t)(half * 32 + o) * NPOS];
        TV[p * 65 + half * 32 + o] = tv[o];
    }
    __syncthreads();
    float acc[32];
    #pragma unroll
    for (int o = 0; o < 32; o++) acc[o] = p2b[half * 32 + o];
    #pragma unroll
    for (int c = 0; c < 64; c++) {
        float xc = TV[p * 65 + c];
        const float4* w4 = (const float4*)(g_p2T + c * 64 + half * 32);
        #pragma unroll
        for (int q = 0; q < 8; q++) {
            float4 w = w4[q];
            acc[q*4+0] += w.x * xc; acc[q*4+1] += w.y * xc;
            acc[q*4+2] += w.z * xc; acc[q*4+3] += w.w * xc;
        }
    }
    const float* sp = g_x5 + (size_t)b * 64 * NPOS + n;
    #pragma unroll
    for (int o = 0; o < 32; o++) {
        int og = half * 32 + o;
        g_y2[((size_t)b * 64 + og) * NPOS + n] = acc[o] + sp[(size_t)og * NPOS];
    }
}

// ---------------- final: permuted gather + LN2 + out matvec; 2 halves ----------------
__global__ void __launch_bounds__(256) k_final(const float* __restrict__ w2,
        const float* __restrict__ b2, const float* __restrict__ ob,
        float* __restrict__ out) {
    int bc = blockIdx.y; int b = bc >> 6, c = bc & 63;
    int s = blockIdx.x * 128 + (threadIdx.x & 127);
    int half = threadIdx.x >> 7;
    const float* yp = g_y2 + (size_t)bc * NPOS;
    float r[64], mean = 0.f;
    #pragma unroll
    for (int j = 0; j < 64; j++) { r[j] = yp[j * 512 + s]; mean += r[j]; }
    mean *= (1.f / 64.f);
    float var = 0.f;
    #pragma unroll
    for (int j = 0; j < 64; j++) { float d = r[j] - mean; var += d * d; }
    float rs = rsqrtf(var * (1.f / 64.f) + 1e-5f);
    float acc[32];
    #pragma unroll
    for (int o = 0; o < 32; o++) acc[o] = ob[half * 32 + o];
    #pragma unroll 1
    for (int j = 0; j < 64; j++) {
        float v = (r[j] - mean) * rs * w2[j] + b2[j];
        const float4* w4 = (const float4*)(g_oT + j * 64 + half * 32);
        #pragma unroll
        for (int q = 0; q < 8; q++) {
            float4 w = w4[q];
            acc[q*4+0] += w.x * v; acc[q*4+1] += w.y * v;
            acc[q*4+2] += w.z * v; acc[q*4+3] += w.w * v;
        }
    }
    float4* op = (float4*)(out + ((size_t)b * NPOS + c + 64 * s) * 64 + half * 32);
    #pragma unroll
    for (int q = 0; q < 8; q++)
        op[q] = make_float4(acc[q*4], acc[q*4+1], acc[q*4+2], acc[q*4+3]);
}

// ---------------- launch ----------------
extern "C" void kernel_launch(void* const* d_in, const int* in_sizes, int n_in,
                              void* d_out, int out_size) {
    const float* x     = (const float*)d_in[0];
    const float* temp  = (const float*)d_in[1];
    const float* qkv_w = (const float*)d_in[2];
    const float* nw    = (const float*)d_in[3];
    const float* nb    = (const float*)d_in[4];
    const float* p1w   = (const float*)d_in[5];
    const float* p1b   = (const float*)d_in[6];
    const float* c0w   = (const float*)d_in[7];
    const float* c0b   = (const float*)d_in[8];
    const float* cspw  = (const float*)d_in[9];
    const float* cspb  = (const float*)d_in[10];
    const float* offw  = (const float*)d_in[11];
    const float* offb  = (const float*)d_in[12];
    const float* dcnw  = (const float*)d_in[13];
    const float* dcnb  = (const float*)d_in[14];
    const float* c1w   = (const float*)d_in[15];
    const float* c1b   = (const float*)d_in[16];
    const float* p2w   = (const float*)d_in[17];
    const float* p2b   = (const float*)d_in[18];
    const float* n2w   = (const float*)d_in[19];
    const float* n2b   = (const float*)d_in[20];
    const float* ow    = (const float*)d_in[21];
    const float* obias = (const float*)d_in[22];
    float* out = (float*)d_out;

    float *qkv, *u, *a, *bb;
    cudaGetSymbolAddress((void**)&qkv, g_qkv);
    cudaGetSymbolAddress((void**)&u,   g_u);
    cudaGetSymbolAddress((void**)&a,   g_a);
    cudaGetSymbolAddress((void**)&bb,  g_b);

    // 1: weight prep + zero attn/scale
    k_prep<<<1193, 256>>>(qkv_w, p1w, c1w, p2w, ow, offw, dcnw, c1b, dcnb);
    // 2: qkv projection (channel-split, 2 halves)
    k_qkv<<<dim3(256, NB), 256>>>(x, qkv);
    // 3: gram + sumsq
    k_gram<<<dim3(128, NB * 4), 256>>>();
    // 4: softmax + attn@v + LN1 + proj1/gelu (channel-split)
    k_xca_ln_p1<<<dim3(256, NB), 256>>>(temp, nw, nb, p1b);
    // 5: depthwise 5^3
    k_dw5<<<dim3(16, NB * 64), 256>>>(u, c0w, c0b, a);
    // 6: depthwise 7^3 dil 3
    k_dw7<<<dim3(12, NB * 64), 256>>>(a, cspw, cspb, bb);
    // 7: channels-last bf16 copy
    k_to_cl<<<dim3(512, NB), 256>>>(bb);
    // 8: fused offsets conv + deformable conv (warp-autonomous, no block barriers)
    k_offdcn_mma<<<dim3(256, NB), 256>>>(offb);
    // 9: conv1*u then proj2+shortcut (channel-split)
    k_c1p2<<<dim3(256, NB), 256>>>(p2b);
    // 10: permute + LN2 + output projection (channel-split)
    k_final<<<dim3(4, NB * 64), 256>>>(n2w, n2b, obias, out);
}